// round 6
// baseline (speedup 1.0000x reference)
#include <cuda_runtime.h>

// Problem constants
#define B        8
#define IN_CH    64
#define OUT_CH   64
#define GROUPS   8
#define FPG      8
#define H        256
#define W        256
#define PLANE    (H * W)
#define REP_DIM  32
#define K9_PER_B (OUT_CH * 9)   // 576

#define TILE     64
#define SSTRIDE  72      // padded smem row stride (float4-friendly)
#define SINT     4       // interior column base in S (left halo at col 3)
#define THREADS  256

// Dynamic per-sample kernels: [B][OUT_CH][9]
__device__ float g_k9[B * K9_PER_B];

// ---------------------------------------------------------------------------
// Kernel 1: k9 = leaky_relu(rep @ W^T, 0.1)
// ---------------------------------------------------------------------------
__global__ void compute_k9_kernel(const float* __restrict__ rep,
                                  const float* __restrict__ Wm) {
    int j = blockIdx.x * blockDim.x + threadIdx.x;
    if (j >= B * K9_PER_B) return;
    int b = j / K9_PER_B;
    int f = j - b * K9_PER_B;
    const float* r = rep + b * REP_DIM;
    const float* w = Wm + f * REP_DIM;
    float s = 0.f;
#pragma unroll
    for (int i = 0; i < REP_DIM; i++) s = fmaf(r[i], w[i], s);
    g_k9[j] = (s > 0.f) ? s : 0.1f * s;
}

// ---------------------------------------------------------------------------
// Kernel 2: fused group-sum + per-channel 3x3 stencil, reflect padding.
// grid: (16 tiles, GROUPS, B), 256 threads, 64x64 tile.
// Load phase: interior via LDG.128 (tx is 64-aligned), halo cols scalar.
// Compute: each thread = 4 cols x 16 rows x 2 channels, STG.128 streaming.
// ---------------------------------------------------------------------------
__device__ __forceinline__ int reflect_idx(int i) {
    i = (i < 0) ? -i : i;
    return (i > H - 1) ? (2 * (H - 1) - i) : i;
}

__global__ __launch_bounds__(THREADS, 4)
void dyn_conv_kernel(const float* __restrict__ x,
                     float* __restrict__ out) {
    const int b = blockIdx.z;
    const int g = blockIdx.y;
    const int ty = (blockIdx.x >> 2) * TILE;
    const int tx = (blockIdx.x & 3) * TILE;
    const int tid = threadIdx.x;

    __shared__ float S[66 * SSTRIDE];    // group-sum tile + halo
    __shared__ float k9s[FPG * 9];

    if (tid < FPG * 9) {
        k9s[tid] = g_k9[b * K9_PER_B + (g * FPG) * 9 + tid];
    }

    const float* xbase = x + ((size_t)(b * IN_CH + g * FPG)) * PLANE;

    // ---- Interior: 66 rows x 16 float4 (columns tx..tx+63, 16B aligned) ----
#pragma unroll
    for (int it = 0; it < 5; it++) {
        int i = tid + it * THREADS;
        if (i < 66 * 16) {
            int row = i >> 4;
            int c4  = i & 15;
            int gy = reflect_idx(ty + row - 1);
            const float* p = xbase + gy * W + tx + c4 * 4;
            float4 s = make_float4(0.f, 0.f, 0.f, 0.f);
#pragma unroll
            for (int c = 0; c < FPG; c++) {
                float4 v = *(const float4*)(p + c * PLANE);
                s.x += v.x; s.y += v.y; s.z += v.z; s.w += v.w;
            }
            *(float4*)&S[row * SSTRIDE + SINT + c4 * 4] = s;
        }
    }

    // ---- Halo columns: 66 rows x 2 sides, scalar ----
    if (tid < 132) {
        int row  = tid >> 1;
        int side = tid & 1;
        int gy = reflect_idx(ty + row - 1);
        int gx = side ? reflect_idx(tx + 64) : reflect_idx(tx - 1);
        const float* p = xbase + gy * W + gx;
        float s = 0.f;
#pragma unroll
        for (int c = 0; c < FPG; c++) s += p[c * PLANE];
        S[row * SSTRIDE + (side ? (SINT + 64) : (SINT - 1))] = s;
    }
    __syncthreads();

    // ---- Compute: thread = (xq, strip, chq) -> 4 cols, 16 rows, 2 channels
    const int xq    = tid & 15;          // 0..15 -> output cols xq*4..xq*4+3
    const int strip = (tid >> 4) & 3;    // 0..3  -> rows strip*16..+15
    const int chq   = tid >> 6;          // 0..3  -> channels chq*2, chq*2+1
    const int lx0   = xq * 4;
    const int y0    = strip * 16;
    const int co0   = chq * 2;

    float kr[18];
#pragma unroll
    for (int c = 0; c < 2; c++)
#pragma unroll
        for (int t = 0; t < 9; t++)
            kr[c * 9 + t] = k9s[(co0 + c) * 9 + t];

    // Sliding 3-row window of 6 S values (S cols lx0+3 .. lx0+8)
    float w0[6], w1[6], w2[6];
    {
        const float* Sp = &S[y0 * SSTRIDE + lx0 + 3];
#pragma unroll
        for (int j = 0; j < 6; j++) w0[j] = Sp[j];
        Sp += SSTRIDE;
#pragma unroll
        for (int j = 0; j < 6; j++) w1[j] = Sp[j];
    }

    float* op = out + ((size_t)(b * OUT_CH + g * FPG + co0)) * PLANE
                    + (ty + y0) * W + tx + lx0;

#pragma unroll 4
    for (int y = 0; y < 16; y++) {
        const float* Sp = &S[(y0 + y + 2) * SSTRIDE + lx0 + 3];
#pragma unroll
        for (int j = 0; j < 6; j++) w2[j] = Sp[j];

#pragma unroll
        for (int c = 0; c < 2; c++) {
            const float* k = &kr[c * 9];
            float4 r;
            r.x = k[0] * w0[0]; r.y = k[0] * w0[1];
            r.z = k[0] * w0[2]; r.w = k[0] * w0[3];
            r.x = fmaf(k[1], w0[1], r.x); r.y = fmaf(k[1], w0[2], r.y);
            r.z = fmaf(k[1], w0[3], r.z); r.w = fmaf(k[1], w0[4], r.w);
            r.x = fmaf(k[2], w0[2], r.x); r.y = fmaf(k[2], w0[3], r.y);
            r.z = fmaf(k[2], w0[4], r.z); r.w = fmaf(k[2], w0[5], r.w);
            r.x = fmaf(k[3], w1[0], r.x); r.y = fmaf(k[3], w1[1], r.y);
            r.z = fmaf(k[3], w1[2], r.z); r.w = fmaf(k[3], w1[3], r.w);
            r.x = fmaf(k[4], w1[1], r.x); r.y = fmaf(k[4], w1[2], r.y);
            r.z = fmaf(k[4], w1[3], r.z); r.w = fmaf(k[4], w1[4], r.w);
            r.x = fmaf(k[5], w1[2], r.x); r.y = fmaf(k[5], w1[3], r.y);
            r.z = fmaf(k[5], w1[4], r.z); r.w = fmaf(k[5], w1[5], r.w);
            r.x = fmaf(k[6], w2[0], r.x); r.y = fmaf(k[6], w2[1], r.y);
            r.z = fmaf(k[6], w2[2], r.z); r.w = fmaf(k[6], w2[3], r.w);
            r.x = fmaf(k[7], w2[1], r.x); r.y = fmaf(k[7], w2[2], r.y);
            r.z = fmaf(k[7], w2[3], r.z); r.w = fmaf(k[7], w2[4], r.w);
            r.x = fmaf(k[8], w2[2], r.x); r.y = fmaf(k[8], w2[3], r.y);
            r.z = fmaf(k[8], w2[4], r.z); r.w = fmaf(k[8], w2[5], r.w);
            __stcs((float4*)(op + c * PLANE), r);
        }
        op += W;
#pragma unroll
        for (int j = 0; j < 6; j++) { w0[j] = w1[j]; w1[j] = w2[j]; }
    }
}

// ---------------------------------------------------------------------------
// Launch
// ---------------------------------------------------------------------------
extern "C" void kernel_launch(void* const* d_in, const int* in_sizes, int n_in,
                              void* d_out, int out_size) {
    const float* x   = (const float*)d_in[0];   // [8, 64, 256, 256]
    const float* rep = (const float*)d_in[1];   // [8, 32]
    const float* Wm  = (const float*)d_in[2];   // [576, 32]
    float* out = (float*)d_out;                 // [8, 64, 256, 256]

    (void)in_sizes; (void)n_in; (void)out_size;

    compute_k9_kernel<<<(B * K9_PER_B + 255) / 256, 256>>>(rep, Wm);

    dim3 grid(16, GROUPS, B);
    dyn_conv_kernel<<<grid, THREADS>>>(x, out);
}

// round 7
// speedup vs baseline: 1.1050x; 1.1050x over previous
#include <cuda_runtime.h>

// Problem constants
#define B        8
#define IN_CH    64
#define OUT_CH   64
#define GROUPS   8
#define FPG      8
#define H        256
#define W        256
#define PLANE    (H * W)
#define REP_DIM  32

#define TILE     64
#define SSTRIDE  72      // padded smem row stride (float4-friendly)
#define SINT     4       // interior column base in S (left halo at col 3)
#define THREADS  256

// ---------------------------------------------------------------------------
// Single fused kernel:
//  - threads 0..71 compute this (b,g)'s 72 dynamic weights
//      k9[c][t] = leaky_relu(rep[b] . W[(g*8+c)*9+t], 0.1)
//  - all threads build S = sum of the group's 8 input channels (reflect halo)
//  - register-tiled 3x3 stencil: thread = 4 cols x 16 rows x 2 channels
// grid: (16 tiles, GROUPS, B), 256 threads, 64x64 tile.
// ---------------------------------------------------------------------------
__device__ __forceinline__ int reflect_idx(int i) {
    i = (i < 0) ? -i : i;
    return (i > H - 1) ? (2 * (H - 1) - i) : i;
}

__global__ __launch_bounds__(THREADS, 4)
void dyn_conv_kernel(const float* __restrict__ x,
                     const float* __restrict__ rep,
                     const float* __restrict__ Wm,
                     float* __restrict__ out) {
    const int b = blockIdx.z;
    const int g = blockIdx.y;
    const int ty = (blockIdx.x >> 2) * TILE;
    const int tx = (blockIdx.x & 3) * TILE;
    const int tid = threadIdx.x;

    __shared__ float S[66 * SSTRIDE];    // group-sum tile + halo
    __shared__ float k9s[FPG * 9];

    // ---- Dynamic weights: 72 dot-products of length 32 (threads 0..71) ----
    if (tid < FPG * 9) {
        const int f = (g * FPG) * 9 + tid;           // row of W
        const float4* r4 = (const float4*)(rep + b * REP_DIM);
        const float4* w4 = (const float4*)(Wm + (size_t)f * REP_DIM);
        float s = 0.f;
#pragma unroll
        for (int i = 0; i < REP_DIM / 4; i++) {
            float4 rv = __ldg(&r4[i]);
            float4 wv = __ldg(&w4[i]);
            s = fmaf(rv.x, wv.x, s);
            s = fmaf(rv.y, wv.y, s);
            s = fmaf(rv.z, wv.z, s);
            s = fmaf(rv.w, wv.w, s);
        }
        k9s[tid] = (s > 0.f) ? s : 0.1f * s;
    }

    const float* xbase = x + ((size_t)(b * IN_CH + g * FPG)) * PLANE;

    // ---- Interior: 66 rows x 16 float4 (columns tx..tx+63, 16B aligned) ----
#pragma unroll
    for (int it = 0; it < 5; it++) {
        int i = tid + it * THREADS;
        if (i < 66 * 16) {
            int row = i >> 4;
            int c4  = i & 15;
            int gy = reflect_idx(ty + row - 1);
            const float* p = xbase + gy * W + tx + c4 * 4;
            float4 s = make_float4(0.f, 0.f, 0.f, 0.f);
#pragma unroll
            for (int c = 0; c < FPG; c++) {
                float4 v = *(const float4*)(p + c * PLANE);
                s.x += v.x; s.y += v.y; s.z += v.z; s.w += v.w;
            }
            *(float4*)&S[row * SSTRIDE + SINT + c4 * 4] = s;
        }
    }

    // ---- Halo columns: 66 rows x 2 sides, scalar ----
    if (tid < 132) {
        int row  = tid >> 1;
        int side = tid & 1;
        int gy = reflect_idx(ty + row - 1);
        int gx = side ? reflect_idx(tx + 64) : reflect_idx(tx - 1);
        const float* p = xbase + gy * W + gx;
        float s = 0.f;
#pragma unroll
        for (int c = 0; c < FPG; c++) s += p[c * PLANE];
        S[row * SSTRIDE + (side ? (SINT + 64) : (SINT - 1))] = s;
    }
    __syncthreads();

    // ---- Compute: thread = (xq, strip, chq) -> 4 cols, 16 rows, 2 channels
    const int xq    = tid & 15;          // 0..15 -> output cols xq*4..xq*4+3
    const int strip = (tid >> 4) & 3;    // 0..3  -> rows strip*16..+15
    const int chq   = tid >> 6;          // 0..3  -> channels chq*2, chq*2+1
    const int lx0   = xq * 4;
    const int y0    = strip * 16;
    const int co0   = chq * 2;

    float kr[18];
#pragma unroll
    for (int c = 0; c < 2; c++)
#pragma unroll
        for (int t = 0; t < 9; t++)
            kr[c * 9 + t] = k9s[(co0 + c) * 9 + t];

    // Sliding 3-row window of 6 S values (S cols lx0+3 .. lx0+8)
    float w0[6], w1[6], w2[6];
    {
        const float* Sp = &S[y0 * SSTRIDE + lx0 + 3];
#pragma unroll
        for (int j = 0; j < 6; j++) w0[j] = Sp[j];
        Sp += SSTRIDE;
#pragma unroll
        for (int j = 0; j < 6; j++) w1[j] = Sp[j];
    }

    float* op = out + ((size_t)(b * OUT_CH + g * FPG + co0)) * PLANE
                    + (ty + y0) * W + tx + lx0;

#pragma unroll 4
    for (int y = 0; y < 16; y++) {
        const float* Sp = &S[(y0 + y + 2) * SSTRIDE + lx0 + 3];
#pragma unroll
        for (int j = 0; j < 6; j++) w2[j] = Sp[j];

#pragma unroll
        for (int c = 0; c < 2; c++) {
            const float* k = &kr[c * 9];
            float4 r;
            r.x = k[0] * w0[0]; r.y = k[0] * w0[1];
            r.z = k[0] * w0[2]; r.w = k[0] * w0[3];
            r.x = fmaf(k[1], w0[1], r.x); r.y = fmaf(k[1], w0[2], r.y);
            r.z = fmaf(k[1], w0[3], r.z); r.w = fmaf(k[1], w0[4], r.w);
            r.x = fmaf(k[2], w0[2], r.x); r.y = fmaf(k[2], w0[3], r.y);
            r.z = fmaf(k[2], w0[4], r.z); r.w = fmaf(k[2], w0[5], r.w);
            r.x = fmaf(k[3], w1[0], r.x); r.y = fmaf(k[3], w1[1], r.y);
            r.z = fmaf(k[3], w1[2], r.z); r.w = fmaf(k[3], w1[3], r.w);
            r.x = fmaf(k[4], w1[1], r.x); r.y = fmaf(k[4], w1[2], r.y);
            r.z = fmaf(k[4], w1[3], r.z); r.w = fmaf(k[4], w1[4], r.w);
            r.x = fmaf(k[5], w1[2], r.x); r.y = fmaf(k[5], w1[3], r.y);
            r.z = fmaf(k[5], w1[4], r.z); r.w = fmaf(k[5], w1[5], r.w);
            r.x = fmaf(k[6], w2[0], r.x); r.y = fmaf(k[6], w2[1], r.y);
            r.z = fmaf(k[6], w2[2], r.z); r.w = fmaf(k[6], w2[3], r.w);
            r.x = fmaf(k[7], w2[1], r.x); r.y = fmaf(k[7], w2[2], r.y);
            r.z = fmaf(k[7], w2[3], r.z); r.w = fmaf(k[7], w2[4], r.w);
            r.x = fmaf(k[8], w2[2], r.x); r.y = fmaf(k[8], w2[3], r.y);
            r.z = fmaf(k[8], w2[4], r.z); r.w = fmaf(k[8], w2[5], r.w);
            __stcs((float4*)(op + c * PLANE), r);
        }
        op += W;
#pragma unroll
        for (int j = 0; j < 6; j++) { w0[j] = w1[j]; w1[j] = w2[j]; }
    }
}

// ---------------------------------------------------------------------------
// Launch: one kernel, no scratch, no inter-kernel bubble.
// ---------------------------------------------------------------------------
extern "C" void kernel_launch(void* const* d_in, const int* in_sizes, int n_in,
                              void* d_out, int out_size) {
    const float* x   = (const float*)d_in[0];   // [8, 64, 256, 256]
    const float* rep = (const float*)d_in[1];   // [8, 32]
    const float* Wm  = (const float*)d_in[2];   // [576, 32]
    float* out = (float*)d_out;                 // [8, 64, 256, 256]

    (void)in_sizes; (void)n_in; (void)out_size;

    dim3 grid(16, GROUPS, B);
    dyn_conv_kernel<<<grid, THREADS>>>(x, rep, Wm, out);
}